// round 3
// baseline (speedup 1.0000x reference)
#include <cuda_runtime.h>
#include <cuda_bf16.h>

// Cumulative mean over axis 0 of x[8192, 4096] fp32:
//   out[r, c] = (sum_{i<=r} x[i, c]) / (r + 1)
//
// Deadlock-free multi-pass scan (no inter-block atomics/spins):
//   k_init    : fill reciprocal table g_inv[r] = 1/(r+1)         (tiny)
//   k_partial : per-tile column sums -> g_part[128][4096]        (reads x)
//   k_scan    : in-place inclusive scan of g_part over tiles     (2 MB, L2)
//   k_final   : out = (exclusive_prefix + running tile scan)*inv (reads x, writes out)

#define ROWS   8192
#define COLS   4096
#define T      64
#define NTILES (ROWS / T)          // 128
#define TPB    128
#define CB_W   (TPB * 4)           // 512 columns per block
#define NCB    (COLS / CB_W)       // 8
#define C4     (COLS / 4)          // 1024 float4 per row

// Scratch (device globals; no allocation allowed anywhere).
__device__ float4 g_part[NTILES * C4];   // [tile][col4] partial sums, 2 MB
__device__ float  g_inv[ROWS];           // 1/(r+1) table, 32 KB

__device__ __forceinline__ float4 f4_add(float4 a, float4 b) {
    a.x += b.x; a.y += b.y; a.z += b.z; a.w += b.w;
    return a;
}

__global__ void k_init() {
    int i = blockIdx.x * blockDim.x + threadIdx.x;
    if (i < ROWS) g_inv[i] = 1.0f / (float)(i + 1);
}

// ---------------- Pass 1: per-tile partial sums ----------------
__global__ void __launch_bounds__(TPB)
k_partial(const float* __restrict__ x) {
    const int rt  = blockIdx.x / NCB;
    const int cb  = blockIdx.x % NCB;
    const int tid = threadIdx.x;

    const float4* __restrict__ x4 = reinterpret_cast<const float4*>(x);
    const int col4 = cb * (CB_W / 4) + tid;
    const int base = rt * T * C4 + col4;

    float4 agg = make_float4(0.f, 0.f, 0.f, 0.f);
#pragma unroll 8
    for (int r = 0; r < T; r++) {
        agg = f4_add(agg, __ldg(&x4[base + r * C4]));
    }
    g_part[rt * C4 + col4] = agg;
}

// ---------------- Pass 2: scan partials over tiles (in place) ----------------
__global__ void __launch_bounds__(TPB)
k_scan() {
    const int t = blockIdx.x * TPB + threadIdx.x;   // 0..1023, one col4 each
    float4 run = make_float4(0.f, 0.f, 0.f, 0.f);
#pragma unroll 4
    for (int rt = 0; rt < NTILES; rt++) {
        const int idx = rt * C4 + t;
        run = f4_add(run, g_part[idx]);
        g_part[idx] = run;                          // inclusive prefix
    }
}

// ---------------- Pass 3: final scan + scale + store ----------------
__global__ void __launch_bounds__(TPB)
k_final(const float* __restrict__ x, float* __restrict__ out) {
    const int rt  = blockIdx.x / NCB;
    const int cb  = blockIdx.x % NCB;
    const int tid = threadIdx.x;

    const float4* __restrict__ x4 = reinterpret_cast<const float4*>(x);
    float4*       __restrict__ o4 = reinterpret_cast<float4*>(out);
    const int col4 = cb * (CB_W / 4) + tid;
    const int base = rt * T * C4 + col4;

    // Exclusive prefix for this tile = inclusive prefix of tile rt-1.
    float4 run = (rt == 0) ? make_float4(0.f, 0.f, 0.f, 0.f)
                           : g_part[(rt - 1) * C4 + col4];

#pragma unroll 8
    for (int r = 0; r < T; r++) {
        float4 v = __ldg(&x4[base + r * C4]);
        run = f4_add(run, v);
        const float inv = __ldg(&g_inv[rt * T + r]);   // warp-uniform, L1-hit
        float4 o;
        o.x = run.x * inv; o.y = run.y * inv;
        o.z = run.z * inv; o.w = run.w * inv;
        o4[base + r * C4] = o;
    }
}

extern "C" void kernel_launch(void* const* d_in, const int* in_sizes, int n_in,
                              void* d_out, int out_size) {
    const float* x   = (const float*)d_in[0];
    float*       out = (float*)d_out;

    k_init<<<(ROWS + 255) / 256, 256>>>();
    k_partial<<<NTILES * NCB, TPB>>>(x);
    k_scan<<<NCB, TPB>>>();
    k_final<<<NTILES * NCB, TPB>>>(x, out);
}